// round 2
// baseline (speedup 1.0000x reference)
#include <cuda_runtime.h>
#include <math.h>

#define B_    4
#define N_    4096
#define C_    512
#define H_    16
#define D_    32
#define M_    (B_*N_)      // 16384
#define KDIM  512
#define NOUT  1024
#define NCHUNK 8
#define CHUNK (N_/NCHUNK)  // 512

// -------- scratch (device globals; no allocations allowed) --------
__device__ float  g_q[M_*C_];                      // elu(q)+1
__device__ float  g_k[M_*C_];                      // elu(k)+1
__device__ float2 g_cs[N_*256];                    // rope cos/sin table
__device__ float  g_kvp[NCHUNK*B_*H_*D_*D_];       // partial kv
__device__ float  g_ksp[NCHUNK*B_*H_*D_];          // partial k sums
__device__ float  g_kv[B_*H_*D_*D_];               // kv (scaled by 1/N)
__device__ float  g_km[B_*H_*D_];                  // kmean

// ============================================================
// RoPE table: emulate JAX fp32 theta & ang, accurate sincos.
// ============================================================
__global__ void rope_table_k() {
    int idx = blockIdx.x * 256 + threadIdx.x;     // N_*256 entries
    int n = idx >> 8;
    int j = idx & 255;
    // theta = 10000^(-j/256) computed in double, rounded to fp32 (matches JAX to ~1 ulp)
    double theta_d = exp((double)j * (-9.210340371976184 / 256.0));
    float  theta   = (float)theta_d;
    float  ang     = (float)n * theta;            // fp32 multiply, like JAX
    // accurate range reduction of the fp32 angle in double
    double a = (double)ang;
    double kq = rint(a * 0.15915494309189535);    // 1/(2*pi)
    double r  = fma(-kq, 6.283185307179586, a);
    float s, c;
    sincosf((float)r, &s, &c);                    // |r| <= pi: accurate even under fast-math
    g_cs[idx] = make_float2(c, s);
}

// ============================================================
// GEMM: qk = x @ Wqk + b, then elu+1 -> g_q / g_k
// 128x128x16 tiles, 256 threads, 8x8 microtile (4+4 split)
// ============================================================
__global__ __launch_bounds__(256) void gemm_act_k(
    const float* __restrict__ X, const float* __restrict__ W,
    const float* __restrict__ bias)
{
    __shared__ __align__(16) float As[16][128];
    __shared__ __align__(16) float Bs[16][128];

    int tid = threadIdx.x;
    int tx  = tid & 15;
    int ty  = tid >> 4;
    int mbase = blockIdx.y * 128;
    int nbase = blockIdx.x * 128;

    const float* xg = X + (size_t)mbase * KDIM;
    const float* wg = W + nbase;

    float acc[8][8];
    #pragma unroll
    for (int i = 0; i < 8; i++)
        #pragma unroll
        for (int jj = 0; jj < 8; jj++) acc[i][jj] = 0.f;

    for (int kt = 0; kt < KDIM; kt += 16) {
        #pragma unroll
        for (int i = 0; i < 2; i++) {
            int idx = tid + i * 256;
            int row = idx >> 2;
            int c4  = (idx & 3) * 4;
            float4 v = *(const float4*)(xg + (size_t)row * KDIM + kt + c4);
            As[c4 + 0][row] = v.x;
            As[c4 + 1][row] = v.y;
            As[c4 + 2][row] = v.z;
            As[c4 + 3][row] = v.w;
        }
        #pragma unroll
        for (int i = 0; i < 2; i++) {
            int idx = tid + i * 256;
            int row = idx >> 5;
            int c4  = (idx & 31) * 4;
            *(float4*)(&Bs[row][c4]) = *(const float4*)(wg + (size_t)(kt + row) * NOUT + c4);
        }
        __syncthreads();

        #pragma unroll
        for (int kk = 0; kk < 16; kk++) {
            float a[8], b[8];
            *(float4*)(a)     = *(const float4*)(&As[kk][ty * 4]);
            *(float4*)(a + 4) = *(const float4*)(&As[kk][ty * 4 + 64]);
            *(float4*)(b)     = *(const float4*)(&Bs[kk][tx * 4]);
            *(float4*)(b + 4) = *(const float4*)(&Bs[kk][tx * 4 + 64]);
            #pragma unroll
            for (int i = 0; i < 8; i++)
                #pragma unroll
                for (int jj = 0; jj < 8; jj++)
                    acc[i][jj] += a[i] * b[jj];
        }
        __syncthreads();
    }

    // epilogue: bias + elu+1, whole 128-col block is entirely q or entirely k
    const bool isq = (nbase < C_);
    float* outp = isq ? g_q : g_k;
    int cb = isq ? nbase : nbase - C_;

    #pragma unroll
    for (int i = 0; i < 8; i++) {
        int row = mbase + ty * 4 + (i & 3) + (i >> 2) * 64;
        #pragma unroll
        for (int jh = 0; jh < 2; jh++) {
            int coff = tx * 4 + jh * 64;
            float4 o;
            float v0 = acc[i][jh * 4 + 0] + bias[nbase + coff + 0];
            float v1 = acc[i][jh * 4 + 1] + bias[nbase + coff + 1];
            float v2 = acc[i][jh * 4 + 2] + bias[nbase + coff + 2];
            float v3 = acc[i][jh * 4 + 3] + bias[nbase + coff + 3];
            o.x = v0 > 0.f ? v0 + 1.f : expf(v0);
            o.y = v1 > 0.f ? v1 + 1.f : expf(v1);
            o.z = v2 > 0.f ? v2 + 1.f : expf(v2);
            o.w = v3 > 0.f ? v3 + 1.f : expf(v3);
            *(float4*)(outp + (size_t)row * C_ + cb + coff) = o;
        }
    }
}

// ============================================================
// kv partials: per (b,h,chunk): kv += k_rope^T v ; ksum += k
// ============================================================
__global__ __launch_bounds__(256) void kv_k(const float* __restrict__ X) {
    int bh = blockIdx.x;              // B_*H_
    int b  = bh >> 4;
    int h  = bh & 15;
    int chunk = blockIdx.y;
    int tid = threadIdx.x;
    int p  = tid & 15;                // pair within head
    int r0 = tid >> 4;                // 0..15

    __shared__ __align__(16) float kr[64][32];
    __shared__ __align__(16) float vs[64][32];
    __shared__ float sred[16][32];

    float4 acc = make_float4(0.f, 0.f, 0.f, 0.f);
    float se = 0.f, so = 0.f;
    int d  = tid >> 3;                // 0..31
    int e0 = (tid & 7) * 4;

    for (int sub = 0; sub < CHUNK; sub += 64) {
        int nb = chunk * CHUNK + sub;
        #pragma unroll
        for (int s = 0; s < 4; s++) {
            int r = r0 + s * 16;
            int n = nb + r;
            size_t base = (size_t)(b * N_ + n) * C_ + h * 32 + 2 * p;
            float2 kp = *(const float2*)(g_k + base);
            float2 cs = g_cs[n * 256 + h * 16 + p];
            se += kp.x; so += kp.y;
            float2 krr = make_float2(kp.x * cs.x - kp.y * cs.y,
                                     kp.x * cs.y + kp.y * cs.x);
            *(float2*)(&kr[r][2 * p]) = krr;
            *(float2*)(&vs[r][2 * p]) = *(const float2*)(X + base);
        }
        __syncthreads();
        #pragma unroll 8
        for (int r = 0; r < 64; r++) {
            float a = kr[r][d];
            float4 v = *(const float4*)(&vs[r][e0]);
            acc.x += a * v.x; acc.y += a * v.y;
            acc.z += a * v.z; acc.w += a * v.w;
        }
        __syncthreads();
    }

    float* kvp = g_kvp + ((size_t)chunk * B_ * H_ + bh) * 1024;
    *(float4*)(kvp + d * 32 + e0) = acc;

    sred[r0][2 * p]     = se;
    sred[r0][2 * p + 1] = so;
    __syncthreads();
    if (tid < 32) {
        float s = 0.f;
        #pragma unroll
        for (int i = 0; i < 16; i++) s += sred[i][tid];
        g_ksp[((size_t)chunk * B_ * H_ + bh) * 32 + tid] = s;
    }
}

// ============================================================
// deterministic reduce of partials, scale by 1/N
// ============================================================
__global__ void kvreduce_k() {
    int i = blockIdx.x * 256 + threadIdx.x;  // B*H*1024 = 65536
    float s = 0.f;
    #pragma unroll
    for (int c = 0; c < NCHUNK; c++) s += g_kvp[(size_t)c * B_ * H_ * 1024 + i];
    g_kv[i] = s * (1.f / N_);
    if (i < B_ * H_ * 32) {
        float t = 0.f;
        #pragma unroll
        for (int c = 0; c < NCHUNK; c++) t += g_ksp[(size_t)c * B_ * H_ * 32 + i];
        g_km[i] = t * (1.f / N_);
    }
}

// ============================================================
// out = (q_rope @ kv) * z + lepe
// block: (n-tile of 32 rows, batch, half of heads)
// ============================================================
__global__ __launch_bounds__(256) void out_k(
    const float* __restrict__ X, const float* __restrict__ lw,
    const float* __restrict__ lb, float* __restrict__ out)
{
    int tile = blockIdx.x;    // N_/32
    int b    = blockIdx.y;
    int half = blockIdx.z;    // 0 or 1 (8 heads each)
    int tid  = threadIdx.x;

    __shared__ __align__(16) float kvs[8 * 1024];   // 32 KB
    __shared__ float kms[256];
    __shared__ float qs[256];
    __shared__ float qrs[256];
    __shared__ float zs[8];

    const float* kvsrc = g_kv + ((size_t)b * 16 + half * 8) * 1024;
    for (int i = tid; i < 8192; i += 256) kvs[i] = kvsrc[i];
    if (tid < 256) kms[tid] = g_km[b * 512 + half * 256 + tid];
    __syncthreads();

    int hl = tid >> 5;        // local head 0..7
    int e  = tid & 31;
    const float* kvh = kvs + hl * 1024;

    for (int r = 0; r < 32; r++) {
        int n = tile * 32 + r;
        size_t row = (size_t)(b * N_ + n) * C_;

        if (tid < 128) {
            float2 qp = *(const float2*)(g_q + row + half * 256 + 2 * tid);
            float2 cs = g_cs[n * 256 + half * 128 + tid];
            qs[2 * tid]      = qp.x;
            qs[2 * tid + 1]  = qp.y;
            qrs[2 * tid]     = qp.x * cs.x - qp.y * cs.y;
            qrs[2 * tid + 1] = qp.x * cs.y + qp.y * cs.x;
        }
        __syncthreads();

        if (tid < 8) {
            float dot = 0.f;
            #pragma unroll
            for (int dd = 0; dd < 32; dd++) dot += qs[tid * 32 + dd] * kms[tid * 32 + dd];
            zs[tid] = 1.f / (dot + 1e-6f);
        }
        __syncthreads();

        float a0 = 0.f;
        const float* qh = qrs + hl * 32;
        #pragma unroll
        for (int dd = 0; dd < 32; dd++)
            a0 += qh[dd] * kvh[dd * 32 + e];
        a0 *= zs[hl];

        int c = half * 256 + tid;   // global channel
        float xc = X[row + c];
        float xm = (n > 0)      ? X[row - C_ + c] : 0.f;
        float xp = (n < N_ - 1) ? X[row + C_ + c] : 0.f;
        float l = xm * lw[c * 3 + 0] + xc * lw[c * 3 + 1] + xp * lw[c * 3 + 2] + lb[c];

        out[row + c] = a0 + l;
        __syncthreads();
    }
}

// ============================================================
extern "C" void kernel_launch(void* const* d_in, const int* in_sizes, int n_in,
                              void* d_out, int out_size) {
    const float* x   = (const float*)d_in[0];
    const float* Wqk = (const float*)d_in[1];
    const float* bqk = (const float*)d_in[2];
    const float* lw  = (const float*)d_in[3];
    const float* lb  = (const float*)d_in[4];
    float* out = (float*)d_out;

    rope_table_k<<<N_ * 256 / 256, 256>>>();
    gemm_act_k<<<dim3(NOUT / 128, M_ / 128), 256>>>(x, Wqk, bqk);
    kv_k<<<dim3(B_ * H_, NCHUNK), 256>>>(x);
    kvreduce_k<<<B_ * H_ * 1024 / 256, 256>>>();
    out_k<<<dim3(N_ / 32, B_, 2), 256>>>(x, lw, lb, out);
}